// round 13
// baseline (speedup 1.0000x reference)
#include <cuda_runtime.h>
#include <math.h>
#include <stdint.h>

#define NG 8
#define GS 16
#define BR 32
#define TT 512
#define NTH 256
typedef unsigned long long ull;

__device__ float g_A[NG][256*BR];
__device__ float g_NOS[NG][64*BR];
__device__ float g_HD[NG][256*BR];
__device__ float g_OBS[NG][64*BR];
__device__ float g_NH0[2][NG][128*BR];
__device__ float g_NH1[2][NG][128*BR];

#define OMUS  0L
#define OSTDS 8388608L
#define ORETS 16777216L
#define OFIN  58720256L

// smem float offsets
#define O_WT1 0
#define O_WT2 1200
#define O_WMS 2228
#define O_WD 4284
#define O_WRZ0 8556
#define O_WIN0 12828
#define O_WHN0 13940
#define O_WRZ1 14972
#define O_WIN1 19084
#define O_WHN1 20116
#define O_B1 21148
#define O_B2 21164
#define O_BS3 21168
#define O_BS4 21200
#define O_BD 21232
#define O_BMS 21248
#define O_X1 21256
#define O_A 23624
#define O_ACT 31816
#define O_X4 40328
#define O_PART 48520
#define O_SCR 50568
#define O_SEQ 51592
#define O_MBAR 51624            // 8 mbarriers (16 floats, 8-byte aligned)
#define SMEM_BYTES (51640*4)

__device__ __forceinline__ ull pk(float w) {
    ull r; asm("mov.b64 %0,{%1,%1};" : "=l"(r) : "f"(w)); return r;
}
__device__ __forceinline__ void fma2(ull& d, ull a, ull b) {
    asm("fma.rn.f32x2 %0,%1,%2,%0;" : "+l"(d) : "l"(a), "l"(b));
}
__device__ __forceinline__ float4 upk(ull lo, ull hi) {
    float4 v; *(ull*)&v.x = lo; *(ull*)&v.z = hi; return v;
}
__device__ __forceinline__ uint32_t smem_u32(const void* p) {
    uint32_t a;
    asm("{ .reg .u64 t; cvta.to.shared.u64 t, %1; cvt.u32.u64 %0, t; }" : "=r"(a) : "l"(p));
    return a;
}

// ---- cluster mbarrier group barrier ----
__device__ __forceinline__ void mbar_arrive_all(uint32_t bar) {
    __syncthreads();                        // all threads' stores ordered before arrives
    if (threadIdx.x < GS) {
        uint32_t rem;
        asm("mapa.shared::cluster.u32 %0, %1, %2;" : "=r"(rem)
            : "r"(bar), "r"((int)threadIdx.x));
        asm volatile("mbarrier.arrive.release.cluster.shared::cluster.b64 _, [%0];"
                     :: "r"(rem) : "memory");
    }
}
__device__ __forceinline__ void mbar_wait(uint32_t bar, uint32_t ph) {
    uint32_t done;
    asm volatile("{\n\t.reg .pred p;\n\t"
        "mbarrier.try_wait.parity.acquire.cluster.shared::cta.b64 p, [%1], %2;\n\t"
        "selp.b32 %0,1,0,p;\n\t}" : "=r"(done) : "r"(bar), "r"(ph) : "memory");
    if (!done) {
        asm volatile("{\n\t.reg .pred P;\n\t"
            "W_%=:\n\t"
            "mbarrier.try_wait.parity.acquire.cluster.shared::cta.b64 P, [%0], %1, 0x989680;\n\t"
            "@P bra D_%=;\n\t"
            "bra W_%=;\n\t"
            "D_%=:\n\t}" :: "r"(bar), "r"(ph) : "memory");
    }
}

// matvec: NCG col-groups x CB cols, KP k-partitions (NCG*KP==32)
template<int NCG,int CB,int KP,int TH>
__device__ __forceinline__ void mv(const float* __restrict__ w, int ldw, int K,
    const float* __restrict__ act, const float* __restrict__ bias,
    float* part, float* dst) {
    const int tid = threadIdx.x, rq = tid & 7, s = tid >> 3;
    const int cg = s % NCG, p = s / NCG;
    const int k0 = p * K / KP, k1 = (p + 1) * K / KP;
    const float* wc = w + cg * CB * ldw;
    ull acc[CB][2];
#pragma unroll
    for (int j = 0; j < CB; j++) { acc[j][0] = 0ull; acc[j][1] = 0ull; }
    __syncthreads();
    const float* ap = act + rq * 4;
#pragma unroll 2
    for (int k = k0; k < k1; k++) {
        ulonglong2 x = *(const ulonglong2*)(ap + k * 32);
#pragma unroll
        for (int j = 0; j < CB; j++) {
            ull wp = pk(wc[j * ldw + k]);
            fma2(acc[j][0], wp, x.x);
            fma2(acc[j][1], wp, x.y);
        }
    }
#pragma unroll
    for (int j = 0; j < CB; j++)
        *(float4*)(part + (s*CB+j)*32 + rq*4) = upk(acc[j][0], acc[j][1]);
    __syncthreads();
    for (int o = tid; o < NCG*CB*32; o += NTH) {
        int c2 = o >> 5, r = o & 31, cg2 = c2 / CB, j = c2 % CB;
        float v = bias[c2];
#pragma unroll
        for (int q = 0; q < KP; q++) v += part[((q*NCG+cg2)*CB+j)*32 + r];
        dst[o] = TH ? tanhf(v) : v;
    }
    __syncthreads();
}

// fused GRU dot: cols 0-15 rz (K=Kx+128), 16-23 in (K=Kx), 24-31 hn (K=128)
__device__ __forceinline__ void grudot(const float* __restrict__ wrz, int ldrz,
    const float* __restrict__ win, int ldin, const float* __restrict__ whn,
    int Kx, const float* __restrict__ act, const float* __restrict__ bias,
    float* part, float* scr) {
    const int tid = threadIdx.x, rq = tid & 7, s = tid >> 3;
    const int cg = s & 15, p = s >> 4;
    const float* wc; int K, ao, ld;
    if (cg < 8)       { wc = wrz + cg*2*ldrz;     K = Kx+128; ao = 0;     ld = ldrz; }
    else if (cg < 12) { wc = win + (cg-8)*2*ldin; K = Kx;     ao = 0;     ld = ldin; }
    else              { wc = whn + (cg-12)*2*129; K = 128;    ao = Kx*32; ld = 129;  }
    const int k0 = p * K / 2, k1 = (p + 1) * K / 2;
    ull a00 = 0ull, a01 = 0ull, a10 = 0ull, a11 = 0ull;
    __syncthreads();
    const float* ap = act + ao + rq * 4;
    for (int k = k0; k < k1; k++) {
        ulonglong2 x = *(const ulonglong2*)(ap + k * 32);
        ull w0 = pk(wc[k]), w1 = pk(wc[ld + k]);
        fma2(a00, w0, x.x); fma2(a01, w0, x.y);
        fma2(a10, w1, x.x); fma2(a11, w1, x.y);
    }
    *(float4*)(part + (s*2)*32 + rq*4)   = upk(a00, a01);
    *(float4*)(part + (s*2+1)*32 + rq*4) = upk(a10, a11);
    __syncthreads();
    for (int o = tid; o < 1024; o += NTH) {
        int c2 = o >> 5, r = o & 31;
        scr[o] = bias[c2] + part[c2*32 + r] + part[(32+c2)*32 + r];
    }
}

__device__ __forceinline__ void cpx(float* d, const float* s, int kc) {
    const float4* s4 = (const float4*)s; float4* d4 = (float4*)d;
#pragma unroll 4
    for (int i = threadIdx.x; i < kc*8; i += NTH) d4[i] = __ldcg(s4 + i);
}
__device__ __forceinline__ void cpx_mask(float* d, const float* s, int kc,
                                         const int* sq, int tp) {
    const float4* s4 = (const float4*)s; float4* d4 = (float4*)d;
#pragma unroll 4
    for (int i = threadIdx.x; i < kc*8; i += NTH) {
        float4 v = __ldcg(s4 + i); int r = (i & 7) * 4;
        if (tp >= sq[r+0]) v.x = 0.f; if (tp >= sq[r+1]) v.y = 0.f;
        if (tp >= sq[r+2]) v.z = 0.f; if (tp >= sq[r+3]) v.w = 0.f;
        d4[i] = v;
    }
}
__device__ __forceinline__ void cpt4(float* d, const float* s, int rs, int K) {
    int K4 = K >> 2;
#pragma unroll 4
    for (int i = threadIdx.x; i < K4*BR; i += NTH) {
        int kq = i % K4, r = i / K4;
        float4 v = *(const float4*)(s + (size_t)r*rs + kq*4);
        d[(kq*4+0)*32+r]=v.x; d[(kq*4+1)*32+r]=v.y;
        d[(kq*4+2)*32+r]=v.z; d[(kq*4+3)*32+r]=v.w;
    }
}
__device__ __forceinline__ void cpt2(float* d, const float* s, int rs, int K) {
    int K2 = K >> 1;
#pragma unroll 4
    for (int i = threadIdx.x; i < K2*BR; i += NTH) {
        int kq = i % K2, r = i / K2;
        float2 v = *(const float2*)(s + (size_t)r*rs + kq*2);
        d[(kq*2+0)*32+r]=v.x; d[(kq*2+1)*32+r]=v.y;
    }
}
__device__ __forceinline__ void ldT(float* d,int ldw,int K,const float* s,int N,int c0,int nc){
    for (int i = threadIdx.x; i < nc*ldw; i += NTH) {
        int c = i / ldw, k = i % ldw;
        d[i] = (k < K) ? s[k*N + c0 + c] : 0.f;
    }
}
__device__ __forceinline__ void ldN(float* d,int ldw,int K,const float* s,int c0,int nc){
    for (int i = threadIdx.x; i < nc*ldw; i += NTH) {
        int c = i / ldw, k = i % ldw;
        d[i] = (k < K) ? s[(c0+c)*K + k] : 0.f;
    }
}
__device__ __forceinline__ void ldRZ(float* d,int ldw,const float* wih,int Kx,
                                     const float* whh,int ct){
    for (int i = threadIdx.x; i < 16*ldw; i += NTH) {
        int c = i / ldw, k = i % ldw;
        int j = (c < 8) ? ct*8 + c : 128 + ct*8 + (c - 8);
        d[i] = (k < Kx) ? wih[j*Kx + k] : ((k < Kx+128) ? whh[j*128 + (k-Kx)] : 0.f);
    }
}
__device__ __forceinline__ float sigf(float x){ return 1.f/(1.f+expf(-x)); }

__global__ void __launch_bounds__(NTH,1)
dynarnn_main(const float* __restrict__ obp, const float* __restrict__ acp,
             const float* __restrict__ noisep, const float* __restrict__ prevp,
             const int* __restrict__ seqp,
             const float* __restrict__ Wih0, const float* __restrict__ Whh0,
             const float* __restrict__ bih0, const float* __restrict__ bhh0,
             const float* __restrict__ Wih1, const float* __restrict__ Whh1,
             const float* __restrict__ bih1, const float* __restrict__ bhh1,
             const float* __restrict__ Wt1p, const float* __restrict__ bt1p,
             const float* __restrict__ Wt2p, const float* __restrict__ bt2p,
             const float* __restrict__ Wd1p, const float* __restrict__ bd1p,
             const float* __restrict__ Wmup, const float* __restrict__ bmup,
             const float* __restrict__ Wsdp, const float* __restrict__ bsdp,
             float* __restrict__ out)
{
    extern __shared__ float sm[];
    const int tid = threadIdx.x;
    const int g = blockIdx.x >> 4;
    int ctr_; asm("mov.u32 %0, %%cluster_ctarank;" : "=r"(ctr_));
    const int ct = ctr_;
    float *wt1 = sm+O_WT1, *wt2 = sm+O_WT2, *wms = sm+O_WMS, *wd = sm+O_WD;
    float *wrz0 = sm+O_WRZ0, *win0 = sm+O_WIN0, *whn0 = sm+O_WHN0;
    float *wrz1 = sm+O_WRZ1, *win1 = sm+O_WIN1, *whn1 = sm+O_WHN1;
    float *b1 = sm+O_B1, *b2 = sm+O_B2, *bS3 = sm+O_BS3, *bS4 = sm+O_BS4;
    float *bd = sm+O_BD, *bms = sm+O_BMS;
    float *sX1 = sm+O_X1, *sA = sm+O_A, *sAct = sm+O_ACT, *sX4 = sm+O_X4;
    float *part = sm+O_PART, *scr = sm+O_SCR;
    int *sseq = (int*)(sm+O_SEQ);
    const uint32_t mb = smem_u32(sm + O_MBAR);

    // mbarrier init + cluster-wide visibility
    if (tid == 0) {
#pragma unroll
        for (int s = 0; s < 8; s++)
            asm volatile("mbarrier.init.shared.b64 [%0], %1;" :: "r"(mb + s*8), "r"(GS) : "memory");
    }
    __syncthreads();
    asm volatile("barrier.cluster.arrive.aligned;" ::: "memory");
    asm volatile("barrier.cluster.wait.aligned;" ::: "memory");

    ldT(wt1, 75, 74, Wt1p, 256, ct*16, 16);
    ldT(wt2, 257, 256, Wt2p, 64, ct*4, 4);
    ldT(wms, 257, 256, Wmup, 64, ct*4, 4);
    ldT(wms + 4*257, 257, 256, Wsdp, 64, ct*4, 4);
    // Wd1 rows permuted so S5 act = [ob|nos|ac|out] reuses S3's buffer
    for (int i = tid; i < 16*267; i += NTH) {
        int c = i / 267, k = i % 267;
        int ko = (k < 64) ? 192 + k : (k < 128) ? 64 + k :
                 (k < 138) ? 128 + k : (k < 266) ? k - 138 : -1;
        wd[i] = (ko >= 0) ? Wd1p[ko*256 + ct*16 + c] : 0.f;
    }
    ldRZ(wrz0, 267, Wih0, 138, Whh0, ct);
    ldRZ(wrz1, 257, Wih1, 128, Whh1, ct);
    ldN(win0, 139, 138, Wih0, 256 + ct*8, 8);
    ldN(whn0, 129, 128, Whh0, 256 + ct*8, 8);
    ldN(win1, 129, 128, Wih1, 256 + ct*8, 8);
    ldN(whn1, 129, 128, Whh1, 256 + ct*8, 8);
    if (tid < 16) {
        b1[tid] = bt1p[ct*16 + tid]; bd[tid] = bd1p[ct*16 + tid];
        int j = (tid < 8) ? ct*8 + tid : 128 + ct*8 + tid - 8;
        bS3[tid] = bih0[j] + bhh0[j]; bS4[tid] = bih1[j] + bhh1[j];
    } else if (tid < 32) {
        int q = tid - 16, j = 256 + ct*8 + (q & 7);
        if (q < 8) { bS3[tid] = bih0[j]; bS4[tid] = bih1[j]; }
        else       { bS3[tid] = bhh0[j]; bS4[tid] = bhh1[j]; }
    }
    if (tid < 4) { b2[tid] = bt2p[ct*4+tid]; bms[tid] = bmup[ct*4+tid]; bms[4+tid] = bsdp[ct*4+tid]; }
    if (tid < BR) sseq[tid] = seqp[g*BR + tid];
    for (int i = tid; i < 8*32; i += NTH) {
        int kk = i >> 5, r = i & 31, k = ct*8 + kk;
        const float* pv = prevp + (size_t)(g*BR + r) * 320;
        g_NH0[0][g][k*32 + r] = pv[k];
        g_NH1[0][g][k*32 + r] = pv[128 + k];
        if (kk < 4) { int k2 = ct*4 + kk; g_OBS[g][k2*32 + r] = pv[256 + k2]; }
    }
    unsigned nb = 0;
#define BAR_A() mbar_arrive_all(mb + (nb&7)*8)
#define BAR_W() do { mbar_wait(mb + (nb&7)*8, (nb>>3)&1); nb++; } while(0)
    BAR_A(); BAR_W();

    for (int t = 0; t < TT; t++) {
        float* nh0rd = g_NH0[t&1][g];       float* nh0wr = g_NH0[(t&1)^1][g];
        float* nh1rd = g_NH1[t&1][g];       float* nh1wr = g_NH1[(t&1)^1][g];
        const float* obT = obp + (size_t)g*BR*TT*64 + (size_t)t*64;
        const float* acT = acp + (size_t)g*BR*TT*10 + (size_t)t*10;
        float eps = 0.f;
        if (tid < 128) {
            size_t b = (size_t)(g*BR + (tid & 31));
            eps = __ldg(noisep + (b*TT + t)*64 + ct*4 + (tid >> 5));
        }
        // S1: a = tanh([obs, ac] @ Wt1 + bt1)
        cpx(sX1, g_OBS[g], 64);
        cpt2(sX1 + 64*32, acT, TT*10, 10);
        mv<8,2,4,1>(wt1, 75, 74, sX1, b1, part, g_A[g] + ct*16*32);
        BAR_A();
        cpt4(sAct, obT, TT*64, 64);
        cpt2(sAct + 128*32, acT, TT*10, 10);
        cpx_mask(sAct + 138*32, nh0rd, 128, sseq, t - 1);   // h0m
        cpx(sX4 + 128*32, nh1rd, 128);                      // h1m
        BAR_W();
        // S2: nos = a @ Wt2 + bt2
        cpx(sA, g_A[g], 256);
        mv<2,2,16,0>(wt2, 257, 256, sA, b2, part, g_NOS[g] + ct*4*32);
        BAR_A(); BAR_W();
        // S3: GRU0
        cpx(sAct + 64*32, g_NOS[g], 64);
        grudot(wrz0, 267, win0, 139, whn0, 138, sAct, bS3, part, scr);
        float hm3; int cg3; size_t bb;
        {
            int c = tid >> 5, r = tid & 31; cg3 = ct*8 + c;
            float rg = sigf(scr[c*32 + r]);
            float zg = sigf(scr[(8+c)*32 + r]);
            float ng = tanhf(scr[(16+c)*32 + r] + rg * scr[(24+c)*32 + r]);
            float hp = sAct[(138 + cg3)*32 + r];
            float nh = (1.f - zg)*ng + zg*hp;
            nh0wr[cg3*32 + r] = nh;
            hm3 = (t < sseq[r]) ? nh : 0.f;
            bb = (size_t)(g*BR + r);
        }
        BAR_A();
        out[ORETS + (bb*TT + t)*320 + cg3] = hm3;
        if (t == TT-1) out[OFIN + bb*320 + cg3] = hm3;
        BAR_W();
        // S4: GRU1
        cpx(sX4, nh0wr, 128);
        grudot(wrz1, 257, win1, 129, whn1, 128, sX4, bS4, part, scr);
        float hm4;
        {
            int c = tid >> 5, r = tid & 31;
            float rg = sigf(scr[c*32 + r]);
            float zg = sigf(scr[(8+c)*32 + r]);
            float ng = tanhf(scr[(16+c)*32 + r] + rg * scr[(24+c)*32 + r]);
            float hp = sX4[(128 + cg3)*32 + r];
            float nh = (1.f - zg)*ng + zg*hp;
            hm4 = (t < sseq[r]) ? nh : 0.f;
            nh1wr[cg3*32 + r] = hm4;
        }
        BAR_A();
        out[ORETS + (bb*TT + t)*320 + 128 + cg3] = hm4;
        if (t == TT-1) out[OFIN + bb*320 + 128 + cg3] = hm4;
        BAR_W();
        // S5: hdec = tanh([ob|nos|ac|out] @ Wd1perm + bd1)
        cpx(sAct + 138*32, nh1wr, 128);
        mv<8,2,4,1>(wd, 267, 266, sAct, bd, part, g_HD[g] + ct*16*32);
        BAR_A(); BAR_W();
        // S6: mu/std/ob_sim
        cpx(sA, g_HD[g], 256);
        mv<4,2,8,0>(wms, 257, 256, sA, bms, part, scr);
        float mu = 0.f, sd = 0.f, obs = 0.f; int cgl = 0;
        if (tid < 128) {
            int c = tid >> 5, r = tid & 31; cgl = ct*4 + c;
            mu = scr[c*32 + r];
            float sv = scr[(4+c)*32 + r];
            sd = fmaxf(sv, 0.f) + log1pf(expf(-fabsf(sv))) + 1e-4f;
            obs = fmaf(sd, eps, mu);
            g_OBS[g][cgl*32 + r] = obs;
        }
        BAR_A();
        if (tid < 128) {
            size_t b = (size_t)(g*BR + (tid & 31));
            out[OMUS  + (b*TT + t)*64 + cgl] = mu;
            out[OSTDS + (b*TT + t)*64 + cgl] = sd;
            out[ORETS + (b*TT + t)*320 + 256 + cgl] = obs;
            if (t == TT-1) out[OFIN + b*320 + 256 + cgl] = obs;
        }
        BAR_W();
    }
}

extern "C" void kernel_launch(void* const* d_in, const int* in_sizes, int n_in,
                              void* d_out, int out_size) {
    cudaFuncSetAttribute(dynarnn_main, cudaFuncAttributeMaxDynamicSharedMemorySize, SMEM_BYTES);
    cudaFuncSetAttribute(dynarnn_main, cudaFuncAttributeNonPortableClusterSizeAllowed, 1);
    const float* a0 = (const float*)d_in[0];  const float* a1 = (const float*)d_in[1];
    const float* a2 = (const float*)d_in[2];  const float* a3 = (const float*)d_in[3];
    const int*   a4 = (const int*)d_in[4];
    const float* a5 = (const float*)d_in[5];  const float* a6 = (const float*)d_in[6];
    const float* a7 = (const float*)d_in[7];  const float* a8 = (const float*)d_in[8];
    const float* a9 = (const float*)d_in[9];  const float* a10 = (const float*)d_in[10];
    const float* a11 = (const float*)d_in[11]; const float* a12 = (const float*)d_in[12];
    const float* a13 = (const float*)d_in[13]; const float* a14 = (const float*)d_in[14];
    const float* a15 = (const float*)d_in[15]; const float* a16 = (const float*)d_in[16];
    const float* a17 = (const float*)d_in[17]; const float* a18 = (const float*)d_in[18];
    const float* a19 = (const float*)d_in[19]; const float* a20 = (const float*)d_in[20];
    const float* a21 = (const float*)d_in[21]; const float* a22 = (const float*)d_in[22];
    float* o = (float*)d_out;

    cudaLaunchConfig_t cfg = {};
    cfg.gridDim = dim3(NG*GS, 1, 1);
    cfg.blockDim = dim3(NTH, 1, 1);
    cfg.dynamicSmemBytes = SMEM_BYTES;
    cudaLaunchAttribute attrs[1];
    attrs[0].id = cudaLaunchAttributeClusterDimension;
    attrs[0].val.clusterDim.x = GS; attrs[0].val.clusterDim.y = 1; attrs[0].val.clusterDim.z = 1;
    cfg.attrs = attrs; cfg.numAttrs = 1;
    cudaLaunchKernelEx(&cfg, dynarnn_main,
        a0,a1,a2,a3,a4,a5,a6,a7,a8,a9,a10,a11,a12,a13,a14,a15,a16,a17,a18,a19,a20,a21,a22,o);
}

// round 15
// speedup vs baseline: 1.9477x; 1.9477x over previous
#include <cuda_runtime.h>
#include <math.h>
#include <stdint.h>

#define NG 8
#define GS 16
#define BR 32
#define TT 512
#define NTH 512

__device__ float g_A[NG][256*BR];
__device__ float g_NOS[NG][64*BR];
__device__ float g_HD[NG][256*BR];
__device__ float g_OBS[NG][64*BR];
__device__ float g_NH0[2][NG][128*BR];
__device__ float g_NH1[2][NG][128*BR];
__device__ unsigned g_ctr[NG];

#define OMUS  0L
#define OSTDS 8388608L
#define ORETS 16777216L
#define OFIN  58720256L

// smem float offsets (weights transposed: [K][C])
#define O_WT1 0
#define O_WT2 1184
#define O_WMS 2208
#define O_WD 4256
#define O_WRZ0 8512
#define O_WIN0 12768
#define O_WHN0 13872
#define O_WRZ1 14896
#define O_WIN1 18992
#define O_WHN1 20016
#define O_B1 21040
#define O_B2 21056
#define O_BS3 21064
#define O_BS4 21096
#define O_BD 21128
#define O_BMS 21144
#define O_X1 21152
#define O_A 23520
#define O_ACT 31712
#define O_X4 40224
#define O_PART 48416
#define O_SCR 50464
#define O_SEQ 51488
#define SMEM_BYTES (51520*4)

__device__ __forceinline__ void bar_arrive(int g) {
    __syncthreads();
    if (threadIdx.x == 0)
        asm volatile("red.release.gpu.global.add.u32 [%0], 1;"
                     :: "l"(&g_ctr[g]) : "memory");
}
__device__ __forceinline__ void bar_wait(int g, unsigned tgt) {
    if (threadIdx.x == 0) {
        unsigned v;
        do {
            asm volatile("ld.acquire.gpu.global.u32 %0, [%1];"
                         : "=r"(v) : "l"(&g_ctr[g]) : "memory");
        } while (v < tgt);
    }
    __syncthreads();
}

// broadcast matvec: weights [K][NQ*4]; lane=row, warp = (q, kpart). NQ*KP==16.
template<int NQ,int KP,int TH>
__device__ __forceinline__ void bmv(const float* __restrict__ w, int K,
    const float* __restrict__ act, const float* __restrict__ bias,
    float* part, float* dst) {
    const int tid = threadIdx.x, lane = tid & 31, wid = tid >> 5;
    const int q = wid % NQ, p = wid / NQ;
    const int k0 = p * K / KP, k1 = (p + 1) * K / KP;
    const float* wp = w + q * 4;
    float4 acc = make_float4(0.f, 0.f, 0.f, 0.f);
    __syncthreads();
    const float* ap = act + lane;
#pragma unroll 4
    for (int k = k0; k < k1; k++) {
        float a = ap[k * 32];
        float4 wv = *(const float4*)(wp + k * (NQ * 4));
        acc.x = fmaf(wv.x, a, acc.x); acc.y = fmaf(wv.y, a, acc.y);
        acc.z = fmaf(wv.z, a, acc.z); acc.w = fmaf(wv.w, a, acc.w);
    }
    part[((q*4+0)*KP + p)*32 + lane] = acc.x;
    part[((q*4+1)*KP + p)*32 + lane] = acc.y;
    part[((q*4+2)*KP + p)*32 + lane] = acc.z;
    part[((q*4+3)*KP + p)*32 + lane] = acc.w;
    __syncthreads();
    for (int o = tid; o < NQ*4*32; o += NTH) {
        int c = o >> 5, r = o & 31;
        float v = bias[c];
#pragma unroll
        for (int p2 = 0; p2 < KP; p2++) v += part[(c*KP + p2)*32 + r];
        dst[o] = TH ? tanhf(v) : v;
    }
    __syncthreads();
}

// fused GRU dots -> scr cols: 0-15 rz (K=Kx+128), 16-23 in (K=Kx), 24-31 hn (K=128)
__device__ __forceinline__ void grudot(const float* __restrict__ wrz,
    const float* __restrict__ win, const float* __restrict__ whn,
    int Kx, const float* __restrict__ act, const float* __restrict__ bias,
    float* part, float* scr) {
    const int tid = threadIdx.x, lane = tid & 31, wid = tid >> 5;
    const float* wp; int K, ao, ldw; float* pb; int q, p;
    if (wid < 8)       { q = wid & 3; p = wid >> 2; wp = wrz + q*4; ldw = 16;
                         K = Kx + 128; ao = 0; pb = part + (q*8 + p)*32; }
    else if (wid < 12) { int u = wid - 8; q = u & 1; p = u >> 1; wp = win + q*4;
                         ldw = 8; K = Kx; ao = 0; pb = part + 1024 + (q*8 + p)*32; }
    else               { int u = wid - 12; q = u & 1; p = u >> 1; wp = whn + q*4;
                         ldw = 8; K = 128; ao = Kx*32; pb = part + 1536 + (q*8 + p)*32; }
    const int k0 = p * K / 2, k1 = (p + 1) * K / 2;
    float4 acc = make_float4(0.f, 0.f, 0.f, 0.f);
    __syncthreads();
    const float* ap = act + ao + lane;
#pragma unroll 4
    for (int k = k0; k < k1; k++) {
        float a = ap[k * 32];
        float4 wv = *(const float4*)(wp + k * ldw);
        acc.x = fmaf(wv.x, a, acc.x); acc.y = fmaf(wv.y, a, acc.y);
        acc.z = fmaf(wv.z, a, acc.z); acc.w = fmaf(wv.w, a, acc.w);
    }
    pb[0*64 + lane] = acc.x;   // (c=q*4+j): index (q*8 + j*2 + p)*32
    pb[1*64 + lane] = acc.y;
    pb[2*64 + lane] = acc.z;
    pb[3*64 + lane] = acc.w;
    __syncthreads();
    for (int o = tid; o < 1024; o += NTH) {
        int c = o >> 5, r = o & 31;
        float v;
        if (c < 16)      v = bias[c] + part[(c*2)*32 + r]     + part[(c*2+1)*32 + r];
        else if (c < 24) { int ci = c-16;
                           v = bias[c] + part[1024 + ci*64 + r] + part[1024 + ci*64 + 32 + r]; }
        else             { int ci = c-24;
                           v = bias[c] + part[1536 + ci*64 + r] + part[1536 + ci*64 + 32 + r]; }
        scr[o] = v;
    }
    __syncthreads();
}

__device__ __forceinline__ void cpx(float* d, const float* s, int kc) {
    const float4* s4 = (const float4*)s; float4* d4 = (float4*)d;
#pragma unroll 4
    for (int i = threadIdx.x; i < kc*8; i += NTH) d4[i] = __ldcg(s4 + i);
}
__device__ __forceinline__ void cpx_mask(float* d, const float* s, int kc,
                                         const int* sq, int tp) {
    const float4* s4 = (const float4*)s; float4* d4 = (float4*)d;
#pragma unroll 4
    for (int i = threadIdx.x; i < kc*8; i += NTH) {
        float4 v = __ldcg(s4 + i); int r = (i & 7) * 4;
        if (tp >= sq[r+0]) v.x = 0.f; if (tp >= sq[r+1]) v.y = 0.f;
        if (tp >= sq[r+2]) v.z = 0.f; if (tp >= sq[r+3]) v.w = 0.f;
        d4[i] = v;
    }
}
__device__ __forceinline__ void cpt4(float* d, const float* s, int rs, int K) {
    int K4 = K >> 2;
#pragma unroll 2
    for (int i = threadIdx.x; i < K4*BR; i += NTH) {
        int kq = i % K4, r = i / K4;
        float4 v = *(const float4*)(s + (size_t)r*rs + kq*4);
        d[(kq*4+0)*32+r]=v.x; d[(kq*4+1)*32+r]=v.y;
        d[(kq*4+2)*32+r]=v.z; d[(kq*4+3)*32+r]=v.w;
    }
}
__device__ __forceinline__ void cpt2(float* d, const float* s, int rs, int K) {
    int K2 = K >> 1;
    for (int i = threadIdx.x; i < K2*BR; i += NTH) {
        int kq = i % K2, r = i / K2;
        float2 v = *(const float2*)(s + (size_t)r*rs + kq*2);
        d[(kq*2+0)*32+r]=v.x; d[(kq*2+1)*32+r]=v.y;
    }
}
__device__ __forceinline__ float sigf(float x){ return 1.f/(1.f+expf(-x)); }

__global__ void dynarnn_init() { if (threadIdx.x < NG) g_ctr[threadIdx.x] = 0u; }

__global__ void __launch_bounds__(NTH,1)
dynarnn_main(const float* __restrict__ obp, const float* __restrict__ acp,
             const float* __restrict__ noisep, const float* __restrict__ prevp,
             const int* __restrict__ seqp,
             const float* __restrict__ Wih0, const float* __restrict__ Whh0,
             const float* __restrict__ bih0, const float* __restrict__ bhh0,
             const float* __restrict__ Wih1, const float* __restrict__ Whh1,
             const float* __restrict__ bih1, const float* __restrict__ bhh1,
             const float* __restrict__ Wt1p, const float* __restrict__ bt1p,
             const float* __restrict__ Wt2p, const float* __restrict__ bt2p,
             const float* __restrict__ Wd1p, const float* __restrict__ bd1p,
             const float* __restrict__ Wmup, const float* __restrict__ bmup,
             const float* __restrict__ Wsdp, const float* __restrict__ bsdp,
             float* __restrict__ out)
{
    extern __shared__ float sm[];
    const int tid = threadIdx.x;
    const int g = blockIdx.x >> 4, ct = blockIdx.x & 15;
    float *wt1 = sm+O_WT1, *wt2 = sm+O_WT2, *wms = sm+O_WMS, *wd = sm+O_WD;
    float *wrz0 = sm+O_WRZ0, *win0 = sm+O_WIN0, *whn0 = sm+O_WHN0;
    float *wrz1 = sm+O_WRZ1, *win1 = sm+O_WIN1, *whn1 = sm+O_WHN1;
    float *b1 = sm+O_B1, *b2 = sm+O_B2, *bS3 = sm+O_BS3, *bS4 = sm+O_BS4;
    float *bd = sm+O_BD, *bms = sm+O_BMS;
    float *sX1 = sm+O_X1, *sA = sm+O_A, *sAct = sm+O_ACT, *sX4 = sm+O_X4;
    float *part = sm+O_PART, *scr = sm+O_SCR;
    int *sseq = (int*)(sm+O_SEQ);

    // ---- weight loads, transposed [K][C] ----
    for (int i = tid; i < 74*16; i += NTH) {
        int k = i >> 4, c = i & 15;
        wt1[i] = Wt1p[k*256 + ct*16 + c];
    }
    for (int i = tid; i < 256*4; i += NTH) {
        int k = i >> 2, c = i & 3;
        wt2[i] = Wt2p[k*64 + ct*4 + c];
    }
    for (int i = tid; i < 256*8; i += NTH) {
        int k = i >> 3, c = i & 7;
        wms[i] = (c < 4) ? Wmup[k*64 + ct*4 + c] : Wsdp[k*64 + ct*4 + (c-4)];
    }
    // Wd1 k-permuted so S5 act = [ob|nos|ac|out] reuses S3's buffer
    for (int i = tid; i < 266*16; i += NTH) {
        int k = i >> 4, c = i & 15;
        int ko = (k < 64) ? 192 + k : (k < 128) ? 64 + k :
                 (k < 138) ? 128 + k : k - 138;
        wd[i] = Wd1p[ko*256 + ct*16 + c];
    }
    for (int i = tid; i < 266*16; i += NTH) {
        int k = i >> 4, c = i & 15;
        int j = (c < 8) ? ct*8 + c : 128 + ct*8 + (c - 8);
        wrz0[i] = (k < 138) ? Wih0[j*138 + k] : Whh0[j*128 + (k - 138)];
    }
    for (int i = tid; i < 256*16; i += NTH) {
        int k = i >> 4, c = i & 15;
        int j = (c < 8) ? ct*8 + c : 128 + ct*8 + (c - 8);
        wrz1[i] = (k < 128) ? Wih1[j*128 + k] : Whh1[j*128 + (k - 128)];
    }
    for (int i = tid; i < 138*8; i += NTH) {
        int k = i >> 3, c = i & 7;
        win0[i] = Wih0[(256 + ct*8 + c)*138 + k];
    }
    for (int i = tid; i < 128*8; i += NTH) {
        int k = i >> 3, c = i & 7;
        whn0[i] = Whh0[(256 + ct*8 + c)*128 + k];
        win1[i] = Wih1[(256 + ct*8 + c)*128 + k];
        whn1[i] = Whh1[(256 + ct*8 + c)*128 + k];
    }
    if (tid < 16) {
        b1[tid] = bt1p[ct*16 + tid]; bd[tid] = bd1p[ct*16 + tid];
        int j = (tid < 8) ? ct*8 + tid : 128 + ct*8 + tid - 8;
        bS3[tid] = bih0[j] + bhh0[j]; bS4[tid] = bih1[j] + bhh1[j];
    } else if (tid < 32) {
        int q = tid - 16, j = 256 + ct*8 + (q & 7);
        if (q < 8) { bS3[tid] = bih0[j]; bS4[tid] = bih1[j]; }
        else       { bS3[tid] = bhh0[j]; bS4[tid] = bhh1[j]; }
    }
    if (tid < 4) { b2[tid] = bt2p[ct*4+tid]; bms[tid] = bmup[ct*4+tid]; bms[4+tid] = bsdp[ct*4+tid]; }
    if (tid < BR) sseq[tid] = seqp[g*BR + tid];
    for (int i = tid; i < 8*32; i += NTH) {
        int kk = i >> 5, r = i & 31, k = ct*8 + kk;
        const float* pv = prevp + (size_t)(g*BR + r) * 320;
        g_NH0[0][g][k*32 + r] = pv[k];
        g_NH1[0][g][k*32 + r] = pv[128 + k];
        if (kk < 4) { int k2 = ct*4 + kk; g_OBS[g][k2*32 + r] = pv[256 + k2]; }
    }
    unsigned nb = 1;
    bar_arrive(g); bar_wait(g, GS*nb); nb++;

    for (int t = 0; t < TT; t++) {
        float* nh0rd = g_NH0[t&1][g];       float* nh0wr = g_NH0[(t&1)^1][g];
        float* nh1rd = g_NH1[t&1][g];       float* nh1wr = g_NH1[(t&1)^1][g];
        const float* obT = obp + (size_t)g*BR*TT*64 + (size_t)t*64;
        const float* acT = acp + (size_t)g*BR*TT*10 + (size_t)t*10;
        float eps = 0.f;
        if (tid < 128) {
            size_t b = (size_t)(g*BR + (tid & 31));
            eps = __ldg(noisep + (b*TT + t)*64 + ct*4 + (tid >> 5));
        }
        // S1: a = tanh([obs, ac] @ Wt1 + bt1)
        cpx(sX1, g_OBS[g], 64);
        cpt2(sX1 + 64*32, acT, TT*10, 10);
        bmv<4,4,1>(wt1, 74, sX1, b1, part, g_A[g] + ct*16*32);
        bar_arrive(g);
        // prefetch S3/S4 inputs inside the barrier-wait shadow
        cpt4(sAct, obT, TT*64, 64);
        cpt2(sAct + 128*32, acT, TT*10, 10);
        cpx_mask(sAct + 138*32, nh0rd, 128, sseq, t - 1);   // h0m
        cpx(sX4 + 128*32, nh1rd, 128);                      // h1m
        bar_wait(g, GS*nb); nb++;
        // S2: nos = a @ Wt2 + bt2
        cpx(sA, g_A[g], 256);
        bmv<1,16,0>(wt2, 256, sA, b2, part, g_NOS[g] + ct*4*32);
        bar_arrive(g); bar_wait(g, GS*nb); nb++;
        // S3: GRU0
        cpx(sAct + 64*32, g_NOS[g], 64);
        grudot(wrz0, win0, whn0, 138, sAct, bS3, part, scr);
        float hm3 = 0.f; int cg3 = 0; size_t bb = 0;
        if (tid < 256) {
            int c = tid >> 5, r = tid & 31; cg3 = ct*8 + c;
            float rg = sigf(scr[c*32 + r]);
            float zg = sigf(scr[(8+c)*32 + r]);
            float ng = tanhf(scr[(16+c)*32 + r] + rg * scr[(24+c)*32 + r]);
            float hp = sAct[(138 + cg3)*32 + r];
            float nh = (1.f - zg)*ng + zg*hp;
            nh0wr[cg3*32 + r] = nh;
            hm3 = (t < sseq[r]) ? nh : 0.f;
            bb = (size_t)(g*BR + r);
        }
        bar_arrive(g);
        if (tid < 256) {
            out[ORETS + (bb*TT + t)*320 + cg3] = hm3;
            if (t == TT-1) out[OFIN + bb*320 + cg3] = hm3;
        }
        bar_wait(g, GS*nb); nb++;
        // S4: GRU1
        cpx(sX4, nh0wr, 128);
        grudot(wrz1, win1, whn1, 128, sX4, bS4, part, scr);
        float hm4 = 0.f;
        if (tid < 256) {
            int c = tid >> 5, r = tid & 31;
            float rg = sigf(scr[c*32 + r]);
            float zg = sigf(scr[(8+c)*32 + r]);
            float ng = tanhf(scr[(16+c)*32 + r] + rg * scr[(24+c)*32 + r]);
            float hp = sX4[(128 + cg3)*32 + r];
            float nh = (1.f - zg)*ng + zg*hp;
            hm4 = (t < sseq[r]) ? nh : 0.f;
            nh1wr[cg3*32 + r] = hm4;
        }
        bar_arrive(g);
        if (tid < 256) {
            out[ORETS + (bb*TT + t)*320 + 128 + cg3] = hm4;
            if (t == TT-1) out[OFIN + bb*320 + 128 + cg3] = hm4;
        }
        bar_wait(g, GS*nb); nb++;
        // S5: hdec = tanh([ob|nos|ac|out] @ Wd1perm + bd1)
        cpx(sAct + 138*32, nh1wr, 128);
        bmv<4,4,1>(wd, 266, sAct, bd, part, g_HD[g] + ct*16*32);
        bar_arrive(g); bar_wait(g, GS*nb); nb++;
        // S6: mu/std/ob_sim
        cpx(sA, g_HD[g], 256);
        bmv<2,8,0>(wms, 256, sA, bms, part, scr);
        float mu = 0.f, sd = 0.f, obs = 0.f; int cgl = 0;
        if (tid < 128) {
            int c = tid >> 5, r = tid & 31; cgl = ct*4 + c;
            mu = scr[c*32 + r];
            float sv = scr[(4+c)*32 + r];
            sd = fmaxf(sv, 0.f) + log1pf(expf(-fabsf(sv))) + 1e-4f;
            obs = fmaf(sd, eps, mu);
            g_OBS[g][cgl*32 + r] = obs;
        }
        bar_arrive(g);
        if (tid < 128) {
            size_t b = (size_t)(g*BR + (tid & 31));
            out[OMUS  + (b*TT + t)*64 + cgl] = mu;
            out[OSTDS + (b*TT + t)*64 + cgl] = sd;
            out[ORETS + (b*TT + t)*320 + 256 + cgl] = obs;
            if (t == TT-1) out[OFIN + b*320 + 256 + cgl] = obs;
        }
        bar_wait(g, GS*nb); nb++;
    }
}

extern "C" void kernel_launch(void* const* d_in, const int* in_sizes, int n_in,
                              void* d_out, int out_size) {
    cudaFuncSetAttribute(dynarnn_main, cudaFuncAttributeMaxDynamicSharedMemorySize, SMEM_BYTES);
    dynarnn_init<<<1, 32>>>();
    dynarnn_main<<<NG*GS, NTH, SMEM_BYTES>>>(
        (const float*)d_in[0], (const float*)d_in[1], (const float*)d_in[2],
        (const float*)d_in[3], (const int*)d_in[4],
        (const float*)d_in[5], (const float*)d_in[6], (const float*)d_in[7],
        (const float*)d_in[8], (const float*)d_in[9], (const float*)d_in[10],
        (const float*)d_in[11], (const float*)d_in[12],
        (const float*)d_in[13], (const float*)d_in[14], (const float*)d_in[15],
        (const float*)d_in[16], (const float*)d_in[17], (const float*)d_in[18],
        (const float*)d_in[19], (const float*)d_in[20], (const float*)d_in[21],
        (const float*)d_in[22], (float*)d_out);
}